// round 3
// baseline (speedup 1.0000x reference)
#include <cuda_runtime.h>
#include <cstdint>
#include <cstddef>

// ---------------- problem constants ----------------
#define BATCH   2
#define NRES    2048
#define NBLADE  16
#define TILE_N  16      // n rows per block
#define MTILE   512     // m rows per block (2 per thread)
#define THREADS 256

typedef unsigned long long ull;

// ---------------- compile-time GP basis table (REV folded in) ----------------
constexpr int cpopc(int x) { int c = 0; while (x) { c += x & 1; x >>= 1; } return c; }

struct Tab {
    signed char sgn[16][16];  // sign of gp term including reverse() on j operand; 0 = absent
    signed char oi [16][16];  // output blade index
};

constexpr Tab make_tab() {
    Tab t{};
    int order[16] = {};
    int p = 0;
    for (int g = 0; g <= 4; ++g)
        for (int bm = 0; bm < 16; ++bm)
            if (cpopc(bm) == g) order[p++] = bm;
    int idx[16] = {};
    for (int i = 0; i < 16; ++i) idx[order[i]] = i;

    for (int j = 0; j < 16; ++j) {
        const int a  = order[j];
        const int gj = cpopc(a);
        const int rev = ((gj * (gj - 1) / 2) % 2) ? -1 : 1;   // reverse sign on operand j
        for (int k = 0; k < 16; ++k) {
            const int b = order[k];
            t.sgn[j][k] = 0;
            t.oi [j][k] = 0;
            if (a & b & 1) continue;            // shared e0 factor -> 0
            int s = 0, tt = a >> 1;
            while (tt) { s += cpopc(tt & b); tt >>= 1; }
            const int sign = (s & 1) ? -1 : 1;
            t.sgn[j][k] = (signed char)(sign * rev);
            t.oi [j][k] = (signed char)idx[a ^ b];
        }
    }
    return t;
}
constexpr Tab TAB = make_tab();

// Bit J set => row J of TAB has at least one negative term (needs negated operand).
constexpr unsigned make_neg_rows() {
    unsigned m = 0;
    for (int j = 0; j < 16; ++j)
        for (int k = 0; k < 16; ++k)
            if (TAB.sgn[j][k] < 0) { m |= (1u << j); break; }
    return m;
}
constexpr unsigned NEG_ROWS = make_neg_rows();

// ---------------- f32x2 packed helpers ----------------
__device__ __forceinline__ ull pack2(float x, float y) {
    ull r;
    asm("mov.b64 %0, {%1, %2};" : "=l"(r) : "f"(x), "f"(y));
    return r;
}
__device__ __forceinline__ void unpack2(ull v, float& x, float& y) {
    asm("mov.b64 {%0, %1}, %2;" : "=f"(x), "=f"(y) : "l"(v));
}
__device__ __forceinline__ void ffma2(ull& d, ull a, ull b) {
    asm("fma.rn.f32x2 %0, %1, %2, %0;" : "+l"(d) : "l"(a), "l"(b));
}

// ---------------- fully-unrolled contraction via template recursion ----------
// All TAB accesses use template parameters -> constant expressions -> no LDC,
// no branches: 192 straight-line FFMA2 instructions.
template <int J, int K>
struct Term {
    static __device__ __forceinline__ void run(ull* acc, ull ap, ull an, const ull* t2) {
        constexpr int s = TAB.sgn[J][K];
        constexpr int o = TAB.oi [J][K];
        if constexpr (s > 0) ffma2(acc[o], ap, t2[K]);
        if constexpr (s < 0) ffma2(acc[o], an, t2[K]);
        if constexpr (K < 15) Term<J, K + 1>::run(acc, ap, an, t2);
    }
};

// Walk J two at a time: one LDS.128 (ulonglong2) yields the packed (a,a)
// operands for J=2Q and J=2Q+1. Negated operands built on the ALU pipe (XOR
// of both sign bits) only when that J-row actually has negative terms.
template <int Q>
struct JPair {
    static __device__ __forceinline__ void run(ull* acc, const ulonglong2* __restrict__ np,
                                               const ull* t2) {
        const ulonglong2 v = np[Q];
        {
            const ull ap = v.x;
            ull an = 0;
            if constexpr ((NEG_ROWS >> (2 * Q)) & 1u) an = ap ^ 0x8000000080000000ULL;
            Term<2 * Q, 0>::run(acc, ap, an, t2);
        }
        {
            const ull ap = v.y;
            ull an = 0;
            if constexpr ((NEG_ROWS >> (2 * Q + 1)) & 1u) an = ap ^ 0x8000000080000000ULL;
            Term<2 * Q + 1, 0>::run(acc, ap, an, t2);
        }
        if constexpr (Q < 7) JPair<Q + 1>::run(acc, np, t2);
    }
};

// ---------------- kernel ----------------
__global__ __launch_bounds__(THREADS)
void grt_pairs_kernel(const float* __restrict__ T, float* __restrict__ out) {
    __shared__ alignas(16) ull sPos[TILE_N][16];   // packed (a,a) per (n, j)

    const int tid = threadIdx.x;
    const int mt  = blockIdx.x;   // m tile: 0..(NRES/MTILE-1)
    const int nt  = blockIdx.y;   // n tile: 0..(NRES/TILE_N-1)
    const int b   = blockIdx.z;   // batch
    const int nbase = nt * TILE_N;

    // Stage the n-tile rows as packed broadcast pairs (a,a).
    {
        const int n = tid >> 4;   // 0..15
        const int j = tid & 15;   // 0..15
        const float a = T[((size_t)b * NRES + (nbase + n)) * NBLADE + j];
        sPos[n][j] = pack2(a, a);
    }

    // Load this thread's two m rows, pack lane-wise into f32x2.
    const int m0 = mt * MTILE + tid;
    const int m1 = m0 + THREADS;
    ull t2[16];
    {
        const float4* r0 = reinterpret_cast<const float4*>(T + ((size_t)b * NRES + m0) * NBLADE);
        const float4* r1 = reinterpret_cast<const float4*>(T + ((size_t)b * NRES + m1) * NBLADE);
#pragma unroll
        for (int q = 0; q < 4; ++q) {
            const float4 x = r0[q];
            const float4 y = r1[q];
            t2[q * 4 + 0] = pack2(x.x, y.x);
            t2[q * 4 + 1] = pack2(x.y, y.y);
            t2[q * 4 + 2] = pack2(x.z, y.z);
            t2[q * 4 + 3] = pack2(x.w, y.w);
        }
    }
    __syncthreads();

    float* const outb = out + (size_t)b * NRES * NRES * NBLADE;

#pragma unroll 1
    for (int nn = 0; nn < TILE_N; ++nn) {
        ull acc[16];
#pragma unroll
        for (int i = 0; i < 16; ++i) acc[i] = 0ULL;  // packed (+0.0f, +0.0f)

        JPair<0>::run(acc, reinterpret_cast<const ulonglong2*>(&sPos[nn][0]), t2);

        float ra[16], rb[16];
#pragma unroll
        for (int i = 0; i < 16; ++i) unpack2(acc[i], ra[i], rb[i]);

        const size_t n = (size_t)(nbase + nn);
        float4* o0 = reinterpret_cast<float4*>(outb + (n * NRES + m0) * NBLADE);
        float4* o1 = reinterpret_cast<float4*>(outb + (n * NRES + m1) * NBLADE);
#pragma unroll
        for (int q = 0; q < 4; ++q) {
            __stcs(o0 + q, make_float4(ra[4 * q + 0], ra[4 * q + 1], ra[4 * q + 2], ra[4 * q + 3]));
            __stcs(o1 + q, make_float4(rb[4 * q + 0], rb[4 * q + 1], rb[4 * q + 2], rb[4 * q + 3]));
        }
    }
}

// ---------------- launch ----------------
extern "C" void kernel_launch(void* const* d_in, const int* in_sizes, int n_in,
                              void* d_out, int out_size) {
    const float* T = (const float*)d_in[0];
    float* out = (float*)d_out;
    (void)in_sizes; (void)n_in; (void)out_size;

    dim3 grid(NRES / MTILE, NRES / TILE_N, BATCH);
    grt_pairs_kernel<<<grid, THREADS>>>(T, out);
}

// round 4
// speedup vs baseline: 1.0379x; 1.0379x over previous
#include <cuda_runtime.h>
#include <cstdint>
#include <cstddef>

// ---------------- problem constants ----------------
#define BATCH   2
#define NRES    2048
#define NBLADE  16
#define TILE_N  16      // n rows per block
#define MTILE   512     // m rows per block (2 per thread)
#define THREADS 256

typedef unsigned long long ull;

// ---------------- compile-time GP basis table (REV folded in) ----------------
constexpr int cpopc(int x) { int c = 0; while (x) { c += x & 1; x >>= 1; } return c; }

struct Tab {
    signed char sgn[16][16];  // sign of gp term including reverse() on j operand; 0 = absent
    signed char oi [16][16];  // output blade index
};

constexpr Tab make_tab() {
    Tab t{};
    int order[16] = {};
    int p = 0;
    for (int g = 0; g <= 4; ++g)
        for (int bm = 0; bm < 16; ++bm)
            if (cpopc(bm) == g) order[p++] = bm;
    int idx[16] = {};
    for (int i = 0; i < 16; ++i) idx[order[i]] = i;

    for (int j = 0; j < 16; ++j) {
        const int a  = order[j];
        const int gj = cpopc(a);
        const int rev = ((gj * (gj - 1) / 2) % 2) ? -1 : 1;   // reverse sign on operand j
        for (int k = 0; k < 16; ++k) {
            const int b = order[k];
            t.sgn[j][k] = 0;
            t.oi [j][k] = 0;
            if (a & b & 1) continue;            // shared e0 factor -> 0
            int s = 0, tt = a >> 1;
            while (tt) { s += cpopc(tt & b); tt >>= 1; }
            const int sign = (s & 1) ? -1 : 1;
            t.sgn[j][k] = (signed char)(sign * rev);
            t.oi [j][k] = (signed char)idx[a ^ b];
        }
    }
    return t;
}
constexpr Tab TAB = make_tab();

// ---------------- f32x2 packed helpers ----------------
__device__ __forceinline__ ull pack2(float x, float y) {
    ull r;
    asm("mov.b64 %0, {%1, %2};" : "=l"(r) : "f"(x), "f"(y));
    return r;
}
__device__ __forceinline__ void unpack2(ull v, float& x, float& y) {
    asm("mov.b64 {%0, %1}, %2;" : "=f"(x), "=f"(y) : "l"(v));
}
__device__ __forceinline__ void ffma2(ull& d, ull a, ull b) {
    asm("fma.rn.f32x2 %0, %1, %2, %0;" : "+l"(d) : "l"(a), "l"(b));
}

// ---------------- fully-unrolled contraction via template recursion ----------
// All TAB accesses are template-parameter indexed -> compile-time constants ->
// 192 straight-line FFMA2, no LDC, no branches.
template <int J, int K>
struct Term {
    static __device__ __forceinline__ void run(ull* acc, ull ap, ull an, const ull* t2) {
        constexpr int s = TAB.sgn[J][K];
        constexpr int o = TAB.oi [J][K];
        if constexpr (s > 0) ffma2(acc[o], ap, t2[K]);
        if constexpr (s < 0) ffma2(acc[o], an, t2[K]);
        if constexpr (K < 15) Term<J, K + 1>::run(acc, ap, an, t2);
    }
};

// Walk J two at a time: one LDS.128 from sPos gives (+a) operands for J=2Q,
// 2Q+1; one LDS.128 from sNeg gives the (-a) operands. Only 4 transient regs.
template <int Q>
struct JPair {
    static __device__ __forceinline__ void run(ull* acc,
                                               const ulonglong2* __restrict__ pp,
                                               const ulonglong2* __restrict__ np,
                                               const ull* t2) {
        const ulonglong2 vp = pp[Q];
        const ulonglong2 vn = np[Q];
        Term<2 * Q,     0>::run(acc, vp.x, vn.x, t2);
        Term<2 * Q + 1, 0>::run(acc, vp.y, vn.y, t2);
        if constexpr (Q < 7) JPair<Q + 1>::run(acc, pp, np, t2);
    }
};

// ---------------- kernel ----------------
__global__ __launch_bounds__(THREADS, 3)
void grt_pairs_kernel(const float* __restrict__ T, float* __restrict__ out) {
    __shared__ alignas(16) ull sPos[TILE_N][16];   // packed (+a, +a) per (n, j)
    __shared__ alignas(16) ull sNeg[TILE_N][16];   // packed (-a, -a) per (n, j)

    const int tid = threadIdx.x;
    const int mt  = blockIdx.x;   // m tile: 0..(NRES/MTILE-1)
    const int nt  = blockIdx.y;   // n tile: 0..(NRES/TILE_N-1)
    const int b   = blockIdx.z;   // batch
    const int nbase = nt * TILE_N;

    // Stage the n-tile rows as packed broadcast pairs.
    {
        const int n = tid >> 4;   // 0..15
        const int j = tid & 15;   // 0..15
        const float a = T[((size_t)b * NRES + (nbase + n)) * NBLADE + j];
        sPos[n][j] = pack2(a, a);
        sNeg[n][j] = pack2(-a, -a);
    }

    // Load this thread's two m rows, pack lane-wise into f32x2.
    const int m0 = mt * MTILE + tid;
    const int m1 = m0 + THREADS;
    ull t2[16];
    {
        const float4* r0 = reinterpret_cast<const float4*>(T + ((size_t)b * NRES + m0) * NBLADE);
        const float4* r1 = reinterpret_cast<const float4*>(T + ((size_t)b * NRES + m1) * NBLADE);
#pragma unroll
        for (int q = 0; q < 4; ++q) {
            const float4 x = r0[q];
            const float4 y = r1[q];
            t2[q * 4 + 0] = pack2(x.x, y.x);
            t2[q * 4 + 1] = pack2(x.y, y.y);
            t2[q * 4 + 2] = pack2(x.z, y.z);
            t2[q * 4 + 3] = pack2(x.w, y.w);
        }
    }
    __syncthreads();

    float* const outb = out + (size_t)b * NRES * NRES * NBLADE;

#pragma unroll 1
    for (int nn = 0; nn < TILE_N; ++nn) {
        ull acc[16];
#pragma unroll
        for (int i = 0; i < 16; ++i) acc[i] = 0ULL;  // packed (+0.0f, +0.0f)

        JPair<0>::run(acc,
                      reinterpret_cast<const ulonglong2*>(&sPos[nn][0]),
                      reinterpret_cast<const ulonglong2*>(&sNeg[nn][0]),
                      t2);

        const size_t n = (size_t)(nbase + nn);
        float4* o0 = reinterpret_cast<float4*>(outb + (n * NRES + m0) * NBLADE);
        float4* o1 = reinterpret_cast<float4*>(outb + (n * NRES + m1) * NBLADE);

        // Interleaved unpack + store: only 8 unpacked floats live at a time.
#pragma unroll
        for (int q = 0; q < 4; ++q) {
            float a0, b0, a1, b1, a2, b2, a3, b3;
            unpack2(acc[4 * q + 0], a0, b0);
            unpack2(acc[4 * q + 1], a1, b1);
            unpack2(acc[4 * q + 2], a2, b2);
            unpack2(acc[4 * q + 3], a3, b3);
            __stcs(o0 + q, make_float4(a0, a1, a2, a3));
            __stcs(o1 + q, make_float4(b0, b1, b2, b3));
        }
    }
}

// ---------------- launch ----------------
extern "C" void kernel_launch(void* const* d_in, const int* in_sizes, int n_in,
                              void* d_out, int out_size) {
    const float* T = (const float*)d_in[0];
    float* out = (float*)d_out;
    (void)in_sizes; (void)n_in; (void)out_size;

    dim3 grid(NRES / MTILE, NRES / TILE_N, BATCH);
    grt_pairs_kernel<<<grid, THREADS>>>(T, out);
}

// round 5
// speedup vs baseline: 1.7502x; 1.6863x over previous
#include <cuda_runtime.h>
#include <cuda.h>
#include <cstdint>
#include <cstddef>

// ---------------- problem constants ----------------
#define BATCH   2
#define NRES    2048
#define NBLADE  16
#define TILE_N  16      // n rows per block
#define MTILE   512     // m rows per block (2 per thread)
#define THREADS 256

typedef unsigned long long ull;

// ---------------- compile-time GP basis table (REV folded in) ----------------
constexpr int cpopc(int x) { int c = 0; while (x) { c += x & 1; x >>= 1; } return c; }

struct Tab {
    signed char sgn[16][16];  // sign of gp term including reverse() on j operand; 0 = absent
    signed char oi [16][16];  // output blade index
};

constexpr Tab make_tab() {
    Tab t{};
    int order[16] = {};
    int p = 0;
    for (int g = 0; g <= 4; ++g)
        for (int bm = 0; bm < 16; ++bm)
            if (cpopc(bm) == g) order[p++] = bm;
    int idx[16] = {};
    for (int i = 0; i < 16; ++i) idx[order[i]] = i;

    for (int j = 0; j < 16; ++j) {
        const int a  = order[j];
        const int gj = cpopc(a);
        const int rev = ((gj * (gj - 1) / 2) % 2) ? -1 : 1;   // reverse sign on operand j
        for (int k = 0; k < 16; ++k) {
            const int b = order[k];
            t.sgn[j][k] = 0;
            t.oi [j][k] = 0;
            if (a & b & 1) continue;            // shared e0 factor -> 0
            int s = 0, tt = a >> 1;
            while (tt) { s += cpopc(tt & b); tt >>= 1; }
            const int sign = (s & 1) ? -1 : 1;
            t.sgn[j][k] = (signed char)(sign * rev);
            t.oi [j][k] = (signed char)idx[a ^ b];
        }
    }
    return t;
}
constexpr Tab TAB = make_tab();

// ---------------- f32x2 packed helpers ----------------
__device__ __forceinline__ ull pack2(float x, float y) {
    ull r;
    asm("mov.b64 %0, {%1, %2};" : "=l"(r) : "f"(x), "f"(y));
    return r;
}
__device__ __forceinline__ void unpack2(ull v, float& x, float& y) {
    asm("mov.b64 {%0, %1}, %2;" : "=f"(x), "=f"(y) : "l"(v));
}
__device__ __forceinline__ void ffma2(ull& d, ull a, ull b) {
    asm("fma.rn.f32x2 %0, %1, %2, %0;" : "+l"(d) : "l"(a), "l"(b));
}

// ---------------- fully-unrolled contraction via template recursion ----------
template <int J, int K>
struct Term {
    static __device__ __forceinline__ void run(ull* acc, ull ap, ull an, const ull* t2) {
        constexpr int s = TAB.sgn[J][K];
        constexpr int o = TAB.oi [J][K];
        if constexpr (s > 0) ffma2(acc[o], ap, t2[K]);
        if constexpr (s < 0) ffma2(acc[o], an, t2[K]);
        if constexpr (K < 15) Term<J, K + 1>::run(acc, ap, an, t2);
    }
};

template <int Q>
struct JPair {
    static __device__ __forceinline__ void run(ull* acc,
                                               const ulonglong2* __restrict__ pp,
                                               const ulonglong2* __restrict__ np,
                                               const ull* t2) {
        const ulonglong2 vp = pp[Q];
        const ulonglong2 vn = np[Q];
        Term<2 * Q,     0>::run(acc, vp.x, vn.x, t2);
        Term<2 * Q + 1, 0>::run(acc, vp.y, vn.y, t2);
        if constexpr (Q < 7) JPair<Q + 1>::run(acc, pp, np, t2);
    }
};

// ---------------- shared computational prologue ----------------
__device__ __forceinline__ void stage_operands_and_rows(
    const float* __restrict__ T, ull* sPos, ull* sNeg, ull* t2,
    int tid, int b, int nbase, int m0, int m1)
{
    {
        const int n = tid >> 4;
        const int j = tid & 15;
        const float a = T[((size_t)b * NRES + (nbase + n)) * NBLADE + j];
        sPos[n * 16 + j] = pack2(a, a);
        sNeg[n * 16 + j] = pack2(-a, -a);
    }
    const float4* r0 = reinterpret_cast<const float4*>(T + ((size_t)b * NRES + m0) * NBLADE);
    const float4* r1 = reinterpret_cast<const float4*>(T + ((size_t)b * NRES + m1) * NBLADE);
#pragma unroll
    for (int q = 0; q < 4; ++q) {
        const float4 x = r0[q];
        const float4 y = r1[q];
        t2[q * 4 + 0] = pack2(x.x, y.x);
        t2[q * 4 + 1] = pack2(x.y, y.y);
        t2[q * 4 + 2] = pack2(x.z, y.z);
        t2[q * 4 + 3] = pack2(x.w, y.w);
    }
}

// =======================================================================
// TMA version: stage 32KB output tile in SW128-swizzled smem, bulk store.
// =======================================================================
#define BUF_BYTES  (32 * 1024)
#define SM_POS_OFF (2 * BUF_BYTES)
#define SM_NEG_OFF (2 * BUF_BYTES + TILE_N * 16 * 8)
#define SMEM_TOTAL (2 * BUF_BYTES + 2 * TILE_N * 16 * 8)

__device__ __forceinline__ uint32_t smem_u32(const void* p) {
    uint32_t a;
    asm("{ .reg .u64 t; cvta.to.shared.u64 t, %1; cvt.u32.u64 %0, t; }" : "=r"(a) : "l"(p));
    return a;
}
__device__ __forceinline__ uint32_t sw128(uint32_t off) {
    return off ^ ((off >> 3) & 0x70u);
}

__global__ __launch_bounds__(THREADS, 3)
void grt_tma_kernel(const float* __restrict__ T, const __grid_constant__ CUtensorMap tmap) {
    extern __shared__ char smem[];
    ull* sPos = reinterpret_cast<ull*>(smem + SM_POS_OFF);
    ull* sNeg = reinterpret_cast<ull*>(smem + SM_NEG_OFF);

    const int tid = threadIdx.x;
    const int mt  = blockIdx.x;
    const int nt  = blockIdx.y;
    const int b   = blockIdx.z;
    const int nbase = nt * TILE_N;

    const int m0 = mt * MTILE + tid;
    const int m1 = m0 + THREADS;
    ull t2[16];
    stage_operands_and_rows(T, sPos, sNeg, t2, tid, b, nbase, m0, m1);
    __syncthreads();

    // Precomputed swizzled staging offsets: rows A at tid*64, B at +16KB.
    const uint32_t offA0 = sw128((uint32_t)tid * 64 + 0);
    const uint32_t offA1 = sw128((uint32_t)tid * 64 + 16);
    const uint32_t offA2 = sw128((uint32_t)tid * 64 + 32);
    const uint32_t offA3 = sw128((uint32_t)tid * 64 + 48);

#pragma unroll 1
    for (int nn = 0; nn < TILE_N; ++nn) {
        ull acc[16];
#pragma unroll
        for (int i = 0; i < 16; ++i) acc[i] = 0ULL;

        JPair<0>::run(acc,
                      reinterpret_cast<const ulonglong2*>(&sPos[nn * 16]),
                      reinterpret_cast<const ulonglong2*>(&sNeg[nn * 16]),
                      t2);

        char* buf = smem + (size_t)(nn & 1) * BUF_BYTES;

        // Make sure the TMA issued 2 iterations ago has drained this buffer.
        if (tid == 0) asm volatile("cp.async.bulk.wait_group 1;" ::: "memory");
        __syncthreads();

        const uint32_t swo[4] = { offA0, offA1, offA2, offA3 };
#pragma unroll
        for (int q = 0; q < 4; ++q) {
            float a0, b0, a1, b1, a2, b2, a3, b3;
            unpack2(acc[4 * q + 0], a0, b0);
            unpack2(acc[4 * q + 1], a1, b1);
            unpack2(acc[4 * q + 2], a2, b2);
            unpack2(acc[4 * q + 3], a3, b3);
            *reinterpret_cast<float4*>(buf + swo[q])         = make_float4(a0, a1, a2, a3);
            *reinterpret_cast<float4*>(buf + swo[q] + 16384) = make_float4(b0, b1, b2, b3);
        }
        __syncthreads();

        if (tid == 0) {
            asm volatile("fence.proxy.async.shared::cta;" ::: "memory");
            const int y = ((b * NRES + (nbase + nn)) << 10) + mt * (MTILE / 2);
            asm volatile(
                "cp.async.bulk.tensor.2d.global.shared::cta.tile.bulk_group [%0, {%1, %2}], [%3];"
                :: "l"(&tmap), "r"(0), "r"(y), "r"(smem_u32(buf)) : "memory");
            asm volatile("cp.async.bulk.commit_group;" ::: "memory");
        }
    }

    if (tid == 0) asm volatile("cp.async.bulk.wait_group 0;" ::: "memory");
}

// =======================================================================
// Fallback (R1-identical): direct streaming STG path.
// =======================================================================
__global__ __launch_bounds__(THREADS, 3)
void grt_stg_kernel(const float* __restrict__ T, float* __restrict__ out) {
    __shared__ alignas(16) ull sPos[TILE_N * 16];
    __shared__ alignas(16) ull sNeg[TILE_N * 16];

    const int tid = threadIdx.x;
    const int mt  = blockIdx.x;
    const int nt  = blockIdx.y;
    const int b   = blockIdx.z;
    const int nbase = nt * TILE_N;

    const int m0 = mt * MTILE + tid;
    const int m1 = m0 + THREADS;
    ull t2[16];
    stage_operands_and_rows(T, sPos, sNeg, t2, tid, b, nbase, m0, m1);
    __syncthreads();

    float* const outb = out + (size_t)b * NRES * NRES * NBLADE;

#pragma unroll 1
    for (int nn = 0; nn < TILE_N; ++nn) {
        ull acc[16];
#pragma unroll
        for (int i = 0; i < 16; ++i) acc[i] = 0ULL;

        JPair<0>::run(acc,
                      reinterpret_cast<const ulonglong2*>(&sPos[nn * 16]),
                      reinterpret_cast<const ulonglong2*>(&sNeg[nn * 16]),
                      t2);

        const size_t n = (size_t)(nbase + nn);
        float4* o0 = reinterpret_cast<float4*>(outb + (n * NRES + m0) * NBLADE);
        float4* o1 = reinterpret_cast<float4*>(outb + (n * NRES + m1) * NBLADE);
#pragma unroll
        for (int q = 0; q < 4; ++q) {
            float a0, b0, a1, b1, a2, b2, a3, b3;
            unpack2(acc[4 * q + 0], a0, b0);
            unpack2(acc[4 * q + 1], a1, b1);
            unpack2(acc[4 * q + 2], a2, b2);
            unpack2(acc[4 * q + 3], a3, b3);
            __stcs(o0 + q, make_float4(a0, a1, a2, a3));
            __stcs(o1 + q, make_float4(b0, b1, b2, b3));
        }
    }
}

// ---------------- launch ----------------
typedef CUresult (*EncodeFn)(CUtensorMap*, CUtensorMapDataType, cuuint32_t, void*,
                             const cuuint64_t*, const cuuint64_t*, const cuuint32_t*,
                             const cuuint32_t*, CUtensorMapInterleave, CUtensorMapSwizzle,
                             CUtensorMapL2promotion, CUtensorMapFloatOOBfill);

extern "C" void kernel_launch(void* const* d_in, const int* in_sizes, int n_in,
                              void* d_out, int out_size) {
    const float* T = (const float*)d_in[0];
    (void)in_sizes; (void)n_in; (void)out_size;

    dim3 grid(NRES / MTILE, NRES / TILE_N, BATCH);

    // Build the output tensormap: 2D [32 floats (=128B pair-row), NPAIRS].
    bool tma_ok = false;
    CUtensorMap tmap;
    {
        void* fn = nullptr;
        cudaDriverEntryPointQueryResult qr = cudaDriverEntryPointSymbolNotFound;
        cudaError_t e = cudaGetDriverEntryPoint("cuTensorMapEncodeTiled", &fn,
                                                cudaEnableDefault, &qr);
        if (e == cudaSuccess && qr == cudaDriverEntryPointSuccess && fn) {
            cuuint64_t dims[2]    = { 32ULL, (cuuint64_t)BATCH * NRES * NRES / 2 };
            cuuint64_t strides[1] = { 128ULL };
            cuuint32_t box[2]     = { 32u, (cuuint32_t)(MTILE / 2) };
            cuuint32_t es[2]      = { 1u, 1u };
            CUresult r = ((EncodeFn)fn)(&tmap, CU_TENSOR_MAP_DATA_TYPE_FLOAT32, 2, d_out,
                                        dims, strides, box, es,
                                        CU_TENSOR_MAP_INTERLEAVE_NONE,
                                        CU_TENSOR_MAP_SWIZZLE_128B,
                                        CU_TENSOR_MAP_L2_PROMOTION_L2_128B,
                                        CU_TENSOR_MAP_FLOAT_OOB_FILL_NONE);
            if (r == CUDA_SUCCESS) tma_ok = true;
        }
    }

    if (tma_ok) {
        static bool attr_done = false;
        cudaFuncSetAttribute(grt_tma_kernel, cudaFuncAttributeMaxDynamicSharedMemorySize,
                             SMEM_TOTAL);
        (void)attr_done;
        grt_tma_kernel<<<grid, THREADS, SMEM_TOTAL>>>(T, tmap);
    } else {
        grt_stg_kernel<<<grid, THREADS>>>(T, (float*)d_out);
    }
}

// round 6
// speedup vs baseline: 1.8182x; 1.0389x over previous
#include <cuda_runtime.h>
#include <cuda.h>
#include <cstdint>
#include <cstddef>

// ---------------- problem constants ----------------
#define BATCH   2
#define NRES    2048
#define NBLADE  16
#define TILE_N  16      // n rows per block
#define MTILE   512     // m rows per block (2 per thread)
#define THREADS 256
#define NBUF    3       // staging buffers (deeper TMA store pipeline)

typedef unsigned long long ull;

// ---------------- compile-time GP basis table (REV folded in) ----------------
constexpr int cpopc(int x) { int c = 0; while (x) { c += x & 1; x >>= 1; } return c; }

struct Tab {
    signed char sgn[16][16];  // sign of gp term including reverse() on j operand; 0 = absent
    signed char oi [16][16];  // output blade index
};

constexpr Tab make_tab() {
    Tab t{};
    int order[16] = {};
    int p = 0;
    for (int g = 0; g <= 4; ++g)
        for (int bm = 0; bm < 16; ++bm)
            if (cpopc(bm) == g) order[p++] = bm;
    int idx[16] = {};
    for (int i = 0; i < 16; ++i) idx[order[i]] = i;

    for (int j = 0; j < 16; ++j) {
        const int a  = order[j];
        const int gj = cpopc(a);
        const int rev = ((gj * (gj - 1) / 2) % 2) ? -1 : 1;   // reverse sign on operand j
        for (int k = 0; k < 16; ++k) {
            const int b = order[k];
            t.sgn[j][k] = 0;
            t.oi [j][k] = 0;
            if (a & b & 1) continue;            // shared e0 factor -> 0
            int s = 0, tt = a >> 1;
            while (tt) { s += cpopc(tt & b); tt >>= 1; }
            const int sign = (s & 1) ? -1 : 1;
            t.sgn[j][k] = (signed char)(sign * rev);
            t.oi [j][k] = (signed char)idx[a ^ b];
        }
    }
    return t;
}
constexpr Tab TAB = make_tab();

// ---------------- f32x2 packed helpers ----------------
__device__ __forceinline__ ull pack2(float x, float y) {
    ull r;
    asm("mov.b64 %0, {%1, %2};" : "=l"(r) : "f"(x), "f"(y));
    return r;
}
__device__ __forceinline__ void unpack2(ull v, float& x, float& y) {
    asm("mov.b64 {%0, %1}, %2;" : "=f"(x), "=f"(y) : "l"(v));
}
__device__ __forceinline__ void ffma2(ull& d, ull a, ull b) {
    asm("fma.rn.f32x2 %0, %1, %2, %0;" : "+l"(d) : "l"(a), "l"(b));
}

// ---------------- fully-unrolled contraction via template recursion ----------
template <int J, int K>
struct Term {
    static __device__ __forceinline__ void run(ull* acc, ull ap, ull an, const ull* t2) {
        constexpr int s = TAB.sgn[J][K];
        constexpr int o = TAB.oi [J][K];
        if constexpr (s > 0) ffma2(acc[o], ap, t2[K]);
        if constexpr (s < 0) ffma2(acc[o], an, t2[K]);
        if constexpr (K < 15) Term<J, K + 1>::run(acc, ap, an, t2);
    }
};

template <int Q>
struct JPair {
    static __device__ __forceinline__ void run(ull* acc,
                                               const ulonglong2* __restrict__ pp,
                                               const ulonglong2* __restrict__ np,
                                               const ull* t2) {
        const ulonglong2 vp = pp[Q];
        const ulonglong2 vn = np[Q];
        Term<2 * Q,     0>::run(acc, vp.x, vn.x, t2);
        Term<2 * Q + 1, 0>::run(acc, vp.y, vn.y, t2);
        if constexpr (Q < 7) JPair<Q + 1>::run(acc, pp, np, t2);
    }
};

// ---------------- shared computational prologue ----------------
__device__ __forceinline__ void stage_operands_and_rows(
    const float* __restrict__ T, ull* sPos, ull* sNeg, ull* t2,
    int tid, int b, int nbase, int m0, int m1)
{
    {
        const int n = tid >> 4;
        const int j = tid & 15;
        const float a = T[((size_t)b * NRES + (nbase + n)) * NBLADE + j];
        sPos[n * 16 + j] = pack2(a, a);
        sNeg[n * 16 + j] = pack2(-a, -a);
    }
    const float4* r0 = reinterpret_cast<const float4*>(T + ((size_t)b * NRES + m0) * NBLADE);
    const float4* r1 = reinterpret_cast<const float4*>(T + ((size_t)b * NRES + m1) * NBLADE);
#pragma unroll
    for (int q = 0; q < 4; ++q) {
        const float4 x = r0[q];
        const float4 y = r1[q];
        t2[q * 4 + 0] = pack2(x.x, y.x);
        t2[q * 4 + 1] = pack2(x.y, y.y);
        t2[q * 4 + 2] = pack2(x.z, y.z);
        t2[q * 4 + 3] = pack2(x.w, y.w);
    }
}

// =======================================================================
// TMA version: stage 32KB output tile in SW128-swizzled smem, bulk store.
// Triple-buffered: the buffer being refilled was committed 3 iters ago.
// =======================================================================
#define BUF_BYTES  (32 * 1024)
#define SM_POS_OFF (NBUF * BUF_BYTES)
#define SM_NEG_OFF (NBUF * BUF_BYTES + TILE_N * 16 * 8)
#define SMEM_TOTAL (NBUF * BUF_BYTES + 2 * TILE_N * 16 * 8)

__device__ __forceinline__ uint32_t smem_u32(const void* p) {
    uint32_t a;
    asm("{ .reg .u64 t; cvta.to.shared.u64 t, %1; cvt.u32.u64 %0, t; }" : "=r"(a) : "l"(p));
    return a;
}
__device__ __forceinline__ uint32_t sw128(uint32_t off) {
    return off ^ ((off >> 3) & 0x70u);
}

__global__ __launch_bounds__(THREADS, 2)
void grt_tma_kernel(const float* __restrict__ T, const __grid_constant__ CUtensorMap tmap) {
    extern __shared__ char smem[];
    ull* sPos = reinterpret_cast<ull*>(smem + SM_POS_OFF);
    ull* sNeg = reinterpret_cast<ull*>(smem + SM_NEG_OFF);

    const int tid = threadIdx.x;
    const int mt  = blockIdx.x;
    const int nt  = blockIdx.y;
    const int b   = blockIdx.z;
    const int nbase = nt * TILE_N;

    const int m0 = mt * MTILE + tid;
    const int m1 = m0 + THREADS;
    ull t2[16];
    stage_operands_and_rows(T, sPos, sNeg, t2, tid, b, nbase, m0, m1);
    __syncthreads();

    // Precomputed swizzled staging offsets: rows A at tid*64, B at +16KB.
    const uint32_t offA0 = sw128((uint32_t)tid * 64 + 0);
    const uint32_t offA1 = sw128((uint32_t)tid * 64 + 16);
    const uint32_t offA2 = sw128((uint32_t)tid * 64 + 32);
    const uint32_t offA3 = sw128((uint32_t)tid * 64 + 48);

    int bufidx = 0;

#pragma unroll 1
    for (int nn = 0; nn < TILE_N; ++nn) {
        ull acc[16];
#pragma unroll
        for (int i = 0; i < 16; ++i) acc[i] = 0ULL;

        JPair<0>::run(acc,
                      reinterpret_cast<const ulonglong2*>(&sPos[nn * 16]),
                      reinterpret_cast<const ulonglong2*>(&sNeg[nn * 16]),
                      t2);

        char* buf = smem + (size_t)bufidx * BUF_BYTES;
        bufidx = (bufidx == NBUF - 1) ? 0 : bufidx + 1;

        // Buffer being refilled was committed NBUF iters ago; allow NBUF-1
        // groups outstanding, so this wait is nearly always satisfied.
        if (tid == 0) asm volatile("cp.async.bulk.wait_group %0;" :: "n"(NBUF - 1) : "memory");
        __syncthreads();

        const uint32_t swo[4] = { offA0, offA1, offA2, offA3 };
#pragma unroll
        for (int q = 0; q < 4; ++q) {
            float a0, b0, a1, b1, a2, b2, a3, b3;
            unpack2(acc[4 * q + 0], a0, b0);
            unpack2(acc[4 * q + 1], a1, b1);
            unpack2(acc[4 * q + 2], a2, b2);
            unpack2(acc[4 * q + 3], a3, b3);
            *reinterpret_cast<float4*>(buf + swo[q])         = make_float4(a0, a1, a2, a3);
            *reinterpret_cast<float4*>(buf + swo[q] + 16384) = make_float4(b0, b1, b2, b3);
        }
        __syncthreads();

        if (tid == 0) {
            asm volatile("fence.proxy.async.shared::cta;" ::: "memory");
            const int y = ((b * NRES + (nbase + nn)) << 10) + mt * (MTILE / 2);
            asm volatile(
                "cp.async.bulk.tensor.2d.global.shared::cta.tile.bulk_group [%0, {%1, %2}], [%3];"
                :: "l"(&tmap), "r"(0), "r"(y), "r"(smem_u32(buf)) : "memory");
            asm volatile("cp.async.bulk.commit_group;" ::: "memory");
        }
    }

    if (tid == 0) asm volatile("cp.async.bulk.wait_group 0;" ::: "memory");
    __syncthreads();
}

// =======================================================================
// Fallback (R1-identical): direct streaming STG path.
// =======================================================================
__global__ __launch_bounds__(THREADS, 3)
void grt_stg_kernel(const float* __restrict__ T, float* __restrict__ out) {
    __shared__ alignas(16) ull sPos[TILE_N * 16];
    __shared__ alignas(16) ull sNeg[TILE_N * 16];

    const int tid = threadIdx.x;
    const int mt  = blockIdx.x;
    const int nt  = blockIdx.y;
    const int b   = blockIdx.z;
    const int nbase = nt * TILE_N;

    const int m0 = mt * MTILE + tid;
    const int m1 = m0 + THREADS;
    ull t2[16];
    stage_operands_and_rows(T, sPos, sNeg, t2, tid, b, nbase, m0, m1);
    __syncthreads();

    float* const outb = out + (size_t)b * NRES * NRES * NBLADE;

#pragma unroll 1
    for (int nn = 0; nn < TILE_N; ++nn) {
        ull acc[16];
#pragma unroll
        for (int i = 0; i < 16; ++i) acc[i] = 0ULL;

        JPair<0>::run(acc,
                      reinterpret_cast<const ulonglong2*>(&sPos[nn * 16]),
                      reinterpret_cast<const ulonglong2*>(&sNeg[nn * 16]),
                      t2);

        const size_t n = (size_t)(nbase + nn);
        float4* o0 = reinterpret_cast<float4*>(outb + (n * NRES + m0) * NBLADE);
        float4* o1 = reinterpret_cast<float4*>(outb + (n * NRES + m1) * NBLADE);
#pragma unroll
        for (int q = 0; q < 4; ++q) {
            float a0, b0, a1, b1, a2, b2, a3, b3;
            unpack2(acc[4 * q + 0], a0, b0);
            unpack2(acc[4 * q + 1], a1, b1);
            unpack2(acc[4 * q + 2], a2, b2);
            unpack2(acc[4 * q + 3], a3, b3);
            __stcs(o0 + q, make_float4(a0, a1, a2, a3));
            __stcs(o1 + q, make_float4(b0, b1, b2, b3));
        }
    }
}

// ---------------- launch ----------------
typedef CUresult (*EncodeFn)(CUtensorMap*, CUtensorMapDataType, cuuint32_t, void*,
                             const cuuint64_t*, const cuuint64_t*, const cuuint32_t*,
                             const cuuint32_t*, CUtensorMapInterleave, CUtensorMapSwizzle,
                             CUtensorMapL2promotion, CUtensorMapFloatOOBfill);

extern "C" void kernel_launch(void* const* d_in, const int* in_sizes, int n_in,
                              void* d_out, int out_size) {
    const float* T = (const float*)d_in[0];
    (void)in_sizes; (void)n_in; (void)out_size;

    dim3 grid(NRES / MTILE, NRES / TILE_N, BATCH);

    // Build the output tensormap: 2D [32 floats (=128B pair-row), NPAIRS].
    bool tma_ok = false;
    CUtensorMap tmap;
    {
        void* fn = nullptr;
        cudaDriverEntryPointQueryResult qr = cudaDriverEntryPointSymbolNotFound;
        cudaError_t e = cudaGetDriverEntryPoint("cuTensorMapEncodeTiled", &fn,
                                                cudaEnableDefault, &qr);
        if (e == cudaSuccess && qr == cudaDriverEntryPointSuccess && fn) {
            cuuint64_t dims[2]    = { 32ULL, (cuuint64_t)BATCH * NRES * NRES / 2 };
            cuuint64_t strides[1] = { 128ULL };
            cuuint32_t box[2]     = { 32u, (cuuint32_t)(MTILE / 2) };
            cuuint32_t es[2]      = { 1u, 1u };
            CUresult r = ((EncodeFn)fn)(&tmap, CU_TENSOR_MAP_DATA_TYPE_FLOAT32, 2, d_out,
                                        dims, strides, box, es,
                                        CU_TENSOR_MAP_INTERLEAVE_NONE,
                                        CU_TENSOR_MAP_SWIZZLE_128B,
                                        CU_TENSOR_MAP_L2_PROMOTION_L2_128B,
                                        CU_TENSOR_MAP_FLOAT_OOB_FILL_NONE);
            if (r == CUDA_SUCCESS) tma_ok = true;
        }
    }

    if (tma_ok) {
        cudaFuncSetAttribute(grt_tma_kernel, cudaFuncAttributeMaxDynamicSharedMemorySize,
                             SMEM_TOTAL);
        grt_tma_kernel<<<grid, THREADS, SMEM_TOTAL>>>(T, tmap);
    } else {
        grt_stg_kernel<<<grid, THREADS>>>(T, (float*)d_out);
    }
}